// round 16
// baseline (speedup 1.0000x reference)
#include <cuda_runtime.h>
#include <cstdint>

// Problem shapes (fixed by the dataset)
#define B_  1024
#define V_  50000
#define E_  256
#define L_  17

// HMMA GEMM config: BKC=112 (3x32 + 1x16 col phases), ~50 barriers/split
#define SPLITS   9
#define BKC      112
#define NCHUNKS  447            // ceil(50000/112); last chunk has 48 valid cols
#define MTILE    128
#define NTILE    128
#define TILEW    28672          // one 128x112 bf16 tile
#define STAGE    (4 * TILEW)    // A_hi A_mid B_hi B_mid = 112KB
#define SMEM_REQ (2 * STAGE)    // 224KB double-buffered (1 CTA/SM)

__device__ __align__(128) float g_scratch[SPLITS * B_ * E_];

// ---------------------------------------------------------------------------
// Helpers
// ---------------------------------------------------------------------------
__device__ __forceinline__ uint32_t smem_u32(const void* p) {
    uint32_t a;
    asm("{ .reg .u64 t; cvta.to.shared.u64 t, %1; cvt.u32.u64 %0, t; }"
        : "=r"(a) : "l"(p));
    return a;
}

// 128x112 tile as 8x8 bf16 blocks (128B): block (br,bc) at (br*14+bc)*128,
// row j of block at 16B slot (j ^ (br&7) ^ ((bc&3)<<1)).
// LDSM phases (bc fixed, 8 rows) -> 8 distinct slots -> conflict-free.
// Fill STS phases (2 rows x 4 bc) -> 8 distinct slots -> conflict-free.
// (Same algebra as R9-R15, block stride 14.)
__device__ __forceinline__ uint32_t toff(int r, int c) {
    const int br = r >> 3, bc = c >> 3;
    const int slot = (r & 7) ^ (br & 7) ^ ((bc & 3) << 1);
    return (uint32_t)(((br * 14 + bc) << 7) + (slot << 4) + ((c & 7) << 1));
}

#define LDSM4(d, addr) \
    asm volatile("ldmatrix.sync.aligned.m8n8.x4.shared.b16 {%0,%1,%2,%3}, [%4];" \
        : "=r"((d)[0]), "=r"((d)[1]), "=r"((d)[2]), "=r"((d)[3]) : "r"(addr))

#define MMA16816(c, a, b0, b1) \
    asm volatile("mma.sync.aligned.m16n8k16.row.col.f32.bf16.bf16.f32 " \
        "{%0,%1,%2,%3}, {%4,%5,%6,%7}, {%8,%9}, {%0,%1,%2,%3};" \
        : "+f"((c)[0]), "+f"((c)[1]), "+f"((c)[2]), "+f"((c)[3]) \
        : "r"((a)[0]), "r"((a)[1]), "r"((a)[2]), "r"((a)[3]), "r"(b0), "r"(b1))

#define MMA16816_ZC(c, a, b0, b1, z) \
    asm volatile("mma.sync.aligned.m16n8k16.row.col.f32.bf16.bf16.f32 " \
        "{%0,%1,%2,%3}, {%4,%5,%6,%7}, {%8,%9}, {%10,%11,%12,%13};" \
        : "=f"((c)[0]), "=f"((c)[1]), "=f"((c)[2]), "=f"((c)[3]) \
        : "r"((a)[0]), "r"((a)[1]), "r"((a)[2]), "r"((a)[3]), "r"(b0), "r"(b1), \
          "f"(z), "f"(z), "f"(z), "f"(z))

#define STS128(addr, v) \
    asm volatile("st.shared.v4.b32 [%0], {%1, %2, %3, %4};" \
        :: "r"(addr), "r"((v).x), "r"((v).y), "r"((v).z), "r"((v).w) : "memory")

// 2-way bf16 split of 8 fp32 values -> two bf16x2-packed uint4.
__device__ __forceinline__ void split2(const float f[8], uint4& H, uint4& M) {
    uint32_t hw[4], mw[4];
#pragma unroll
    for (int i = 0; i < 4; i++) {
        const float f0 = f[2 * i], f1 = f[2 * i + 1];
        uint32_t hp;
        asm("cvt.rn.bf16x2.f32 %0, %1, %2;" : "=r"(hp) : "f"(f1), "f"(f0));
        const float h0 = __uint_as_float(hp << 16);
        const float h1 = __uint_as_float(hp & 0xFFFF0000u);
        const float r0 = f0 - h0, r1 = f1 - h1;   // exact (Sterbenz)
        uint32_t mp;
        asm("cvt.rn.bf16x2.f32 %0, %1, %2;" : "=r"(mp) : "f"(r1), "f"(r0));
        hw[i] = hp; mw[i] = mp;
    }
    H = make_uint4(hw[0], hw[1], hw[2], hw[3]);
    M = make_uint4(mw[0], mw[1], mw[2], mw[3]);
}

// ---------------------------------------------------------------------------
// Kernel 1: split-K GEMM via 3-pass bf16-split HMMA (xH@wH + xM@wH + xH@wM),
// per-chunk RN flush vs tensor-core RZ bias. 512 threads, 16 warps of 32x32,
// BKC=112: three 32-col phases (all threads) + one 16-col phase (warps 0-7),
// interleaved into the MMA body.
// ---------------------------------------------------------------------------
__global__ __launch_bounds__(512) void gemm_hmma_kernel(
    const float* __restrict__ x, const float* __restrict__ W)
{
    extern __shared__ __align__(1024) char smem[];
    const uint32_t sm0 = smem_u32(smem);

    const int tid  = threadIdx.x;
    const int lane = tid & 31;
    const int wid  = tid >> 5;            // 0..15
    const int wm   = wid & 3;             // m tile: 32*wm
    const int wn   = wid >> 2;            // n tile: 32*wn

    const int brow  = blockIdx.x;         // 0..7
    const int bcol  = blockIdx.y;         // 0..1
    const int split = blockIdx.z;         // 0..SPLITS-1
    const int c0 = (split * NCHUNKS) / SPLITS;
    const int c1 = ((split + 1) * NCHUNKS) / SPLITS;

    const float* xrow = x + (size_t)(brow * MTILE) * V_;
    const float* wrow = W + (size_t)(bcol * NTILE) * V_;

    // 32-col phase mapping: row fr (0..127), quarter fq (cols fq*8..fq*8+7)
    const int fr = tid >> 2;
    const int fq = tid & 3;
    // 16-col tail phase mapping (threads 0..255): row frT, half fqT
    const int frT = tid >> 1;             // 0..255 -> rows 0..127 (tid<256)
    const int fqT = tid & 1;

    // ldmatrix lane address components
    const int jrA = ((lane >> 3) & 1) * 8 + (lane & 7);
    const int cA  = (lane >> 4) * 8;
    const int nB  = (lane >> 4) * 8 + (lane & 7);
    const int cB  = ((lane >> 3) & 1) * 8;

    float accm[2][4][4];                  // main accumulator (RN FADD)
    float acct[2][4][4];                  // HMMA chunk accumulator
#pragma unroll
    for (int i = 0; i < 2; i++)
#pragma unroll
        for (int j = 0; j < 4; j++)
#pragma unroll
            for (int q = 0; q < 4; q++) accm[i][j][q] = 0.f;

    const float fz = 0.f;
    float fA[8], fB[8];

    // load phase p of chunk c into staging regs (p<3: 32 cols all threads;
    // p==3: 16 cols, threads < 256 only)
    auto load_phase = [&](int c, int p) {
        int r, q8, kb;
        if (p < 3) { r = fr;  q8 = fq;  kb = c * BKC + p * 32; }
        else       { if (tid >= 256) return;
                     r = frT; q8 = fqT; kb = c * BKC + 96; }
        const float* pa = xrow + (size_t)r * V_ + kb + q8 * 8;
        const float* pb = wrow + (size_t)r * V_ + kb + q8 * 8;
        if (kb + q8 * 8 + 8 <= V_) {
#pragma unroll
            for (int i = 0; i < 2; i++) {
                const float4 va = ((const float4*)pa)[i];
                const float4 vb = ((const float4*)pb)[i];
                fA[4 * i + 0] = va.x; fA[4 * i + 1] = va.y;
                fA[4 * i + 2] = va.z; fA[4 * i + 3] = va.w;
                fB[4 * i + 0] = vb.x; fB[4 * i + 1] = vb.y;
                fB[4 * i + 2] = vb.z; fB[4 * i + 3] = vb.w;
            }
        } else {
#pragma unroll
            for (int e = 0; e < 8; e++) {
                const bool ok = (kb + q8 * 8 + e) < V_;
                fA[e] = ok ? pa[e] : 0.f;
                fB[e] = ok ? pb[e] : 0.f;
            }
        }
    };

    // convert staging regs -> bf16 tiles, phase p, stage base sb
    auto sts_phase = [&](uint32_t sb, int p) {
        int r, bc;
        if (p < 3) { r = fr;  bc = p * 4 + fq; }
        else       { if (tid >= 256) return;
                     r = frT; bc = 12 + fqT; }
        const uint32_t o = (uint32_t)((((r >> 3) * 14 + bc) << 7)
            + ((((r & 7) ^ ((r >> 3) & 7) ^ ((bc & 3) << 1))) << 4));
        uint4 H, M;
        split2(fA, H, M);
        STS128(sb + 0 * TILEW + o, H);
        STS128(sb + 1 * TILEW + o, M);
        split2(fB, H, M);
        STS128(sb + 2 * TILEW + o, H);
        STS128(sb + 3 * TILEW + o, M);
    };

    // prologue: fill stage 0 (all four phases)
#pragma unroll
    for (int p = 0; p < 4; p++) {
        load_phase(c0, p);
        sts_phase(sm0, p);
    }
    __syncthreads();

    for (int c = c0; c < c1; ++c) {
        const int li = c - c0;
        const uint32_t sb = sm0 + (uint32_t)(li & 1) * STAGE;
        const uint32_t sn = sm0 + (uint32_t)((li + 1) & 1) * STAGE;
        const bool more = (c + 1 < c1);

        if (more) load_phase(c + 1, 0);       // LDG phase 0 early

        // ---- 7 k-slices x 3 passes; converts interleaved at ki 0,2,4,5 ----
#pragma unroll
        for (int ki = 0; ki < 7; ki++) {
            const int k = ki * 16;
            uint32_t a[2][2][4];
#pragma unroll
            for (int lv = 0; lv < 2; lv++)
#pragma unroll
                for (int mt = 0; mt < 2; mt++)
                    LDSM4(a[lv][mt],
                          sb + lv * TILEW + toff(wm * 32 + mt * 16 + jrA, k + cA));

            uint32_t bH[2][4];
#pragma unroll
            for (int ng = 0; ng < 2; ng++)
                LDSM4(bH[ng], sb + 2 * TILEW
                              + toff(wn * 32 + ng * 16 + nB, k + cB));

            // group 1: A_hi x B_hi (ki==0 seeds the chunk accumulator)
            {
                const bool seed = (ki == 0);
#pragma unroll
                for (int mt = 0; mt < 2; mt++)
#pragma unroll
                    for (int nt = 0; nt < 4; nt++) {
                        if (seed)
                            MMA16816_ZC(acct[mt][nt], a[0][mt],
                                        bH[nt >> 1][(nt & 1) * 2],
                                        bH[nt >> 1][(nt & 1) * 2 + 1], fz);
                        else
                            MMA16816(acct[mt][nt], a[0][mt],
                                     bH[nt >> 1][(nt & 1) * 2],
                                     bH[nt >> 1][(nt & 1) * 2 + 1]);
                    }
            }
            // group 2: A_mid x B_hi
#pragma unroll
            for (int mt = 0; mt < 2; mt++)
#pragma unroll
                for (int nt = 0; nt < 4; nt++)
                    MMA16816(acct[mt][nt], a[1][mt],
                             bH[nt >> 1][(nt & 1) * 2],
                             bH[nt >> 1][(nt & 1) * 2 + 1]);

            uint32_t bM[2][4];
#pragma unroll
            for (int ng = 0; ng < 2; ng++)
                LDSM4(bM[ng], sb + 3 * TILEW
                              + toff(wn * 32 + ng * 16 + nB, k + cB));

            // group 3: A_hi x B_mid
#pragma unroll
            for (int mt = 0; mt < 2; mt++)
#pragma unroll
                for (int nt = 0; nt < 4; nt++)
                    MMA16816(acct[mt][nt], a[0][mt],
                             bM[nt >> 1][(nt & 1) * 2],
                             bM[nt >> 1][(nt & 1) * 2 + 1]);

            // interleave next-chunk converts while MMAs drain
            if (more && ki == 0) { sts_phase(sn, 0); load_phase(c + 1, 1); }
            if (more && ki == 2) { sts_phase(sn, 1); load_phase(c + 1, 2); }
            if (more && ki == 4) { sts_phase(sn, 2); load_phase(c + 1, 3); }
            if (more && ki == 5) { sts_phase(sn, 3); }
        }

        // chunk flush: RN fp32 adds (defeats tensor-core RZ bias)
#pragma unroll
        for (int mt = 0; mt < 2; mt++)
#pragma unroll
            for (int nt = 0; nt < 4; nt++)
#pragma unroll
                for (int q = 0; q < 4; q++)
                    accm[mt][nt][q] += acct[mt][nt][q];

        __syncthreads();
    }

    // epilogue: write fp32 partials
    float* base = g_scratch + (size_t)split * (B_ * E_);
#pragma unroll
    for (int mt = 0; mt < 2; mt++)
#pragma unroll
        for (int nt = 0; nt < 4; nt++) {
            const int row = brow * MTILE + wm * 32 + mt * 16 + (lane >> 2);
            const int col = bcol * NTILE + wn * 32 + nt * 8 + (lane & 3) * 2;
            float2 v0 = make_float2(accm[mt][nt][0], accm[mt][nt][1]);
            float2 v1 = make_float2(accm[mt][nt][2], accm[mt][nt][3]);
            *(float2*)&base[(size_t)row * E_ + col]       = v0;
            *(float2*)&base[(size_t)(row + 8) * E_ + col] = v1;
        }
}

// ---------------------------------------------------------------------------
// Kernel 2 (fused): split-K reduction + bias + per-path dots + signed sigmoid
// + product. One block (4 warps) per batch row; warps split the 17 path
// nodes (5,4,4,4); deterministic combine.
// ---------------------------------------------------------------------------
__global__ __launch_bounds__(128) void path_prod_kernel(
    const float* __restrict__ bias, const float* __restrict__ pv,
    const int* __restrict__ signs, float* __restrict__ out)
{
    __shared__ float part[4];
    const int warp = threadIdx.x >> 5;
    const int lane = threadIdx.x & 31;
    const int b    = blockIdx.x;

    // e[j] = bias + deterministic sum over splits
    float e[8];
#pragma unroll
    for (int j = 0; j < 8; j++) {
        const int col = lane + 32 * j;
        float s = 0.f;
#pragma unroll
        for (int sp = 0; sp < SPLITS; sp++)
            s += g_scratch[(size_t)sp * (B_ * E_) + (size_t)b * E_ + col];
        e[j] = s + bias[col];
    }

    const int l0 = (warp == 0) ? 0 : (5 + (warp - 1) * 4);
    const int l1 = (warp == 0) ? 5 : (l0 + 4);

    float prod = 1.f;
#pragma unroll 1
    for (int l = l0; l < l1; l++) {
        const float* p = pv + ((size_t)b * L_ + l) * E_;
        float d = 0.f;
#pragma unroll
        for (int j = 0; j < 8; j++)
            d += p[lane + 32 * j] * e[j];
#pragma unroll
        for (int off = 16; off; off >>= 1)
            d += __shfl_xor_sync(0xFFFFFFFFu, d, off);

        const int   sg    = signs[b * L_ + l];
        const float logit = d * (float)(2 * sg - 1);

        float sgm;
        if (logit >= 0.f) {
            sgm = 1.f / (1.f + expf(-logit));
        } else {
            const float ex = expf(logit);     // stable tail, matches jax.nn.sigmoid
            sgm = ex / (1.f + ex);
        }
        prod *= sgm;
    }
    if (lane == 0) part[warp] = prod;
    __syncthreads();
    if (threadIdx.x == 0)
        out[b] = ((part[0] * part[1]) * part[2]) * part[3];
}

// ---------------------------------------------------------------------------
// Launch. Inputs (metadata order): x[B*V], W[E*V], b[E], path_vectors[B*L*E],
// path_signs[B*L] (int32). Output: float[B].
// ---------------------------------------------------------------------------
extern "C" void kernel_launch(void* const* d_in, const int* in_sizes, int n_in,
                              void* d_out, int out_size)
{
    const float* x     = (const float*)d_in[0];
    const float* W     = (const float*)d_in[1];
    const float* bias  = (const float*)d_in[2];
    const float* pv    = (const float*)d_in[3];
    const int*   signs = (const int*)  d_in[4];
    float*       out   = (float*)d_out;

    // idempotent attribute set (not a stream op; capture-safe)
    cudaFuncSetAttribute(gemm_hmma_kernel,
                         cudaFuncAttributeMaxDynamicSharedMemorySize, SMEM_REQ);

    dim3 g1(B_ / MTILE, E_ / NTILE, SPLITS);   // (8, 2, 9) = 144 CTAs
    gemm_hmma_kernel<<<g1, 512, SMEM_REQ>>>(x, W);

    path_prod_kernel<<<B_, 128>>>(bias, pv, signs, out);
}

// round 17
// speedup vs baseline: 1.2739x; 1.2739x over previous
#include <cuda_runtime.h>
#include <cstdint>

// Problem shapes (fixed by the dataset)
#define B_  1024
#define V_  50000
#define E_  256
#define L_  17

// HMMA GEMM config: BKC=96 (three 32-col phases per chunk), ~58 barriers/split
#define SPLITS   9
#define BKC      96
#define NCHUNKS  521            // ceil(50000/96); last chunk has 80 valid cols
#define MTILE    128
#define NTILE    128
#define TILEW    24576          // one 128x96 bf16 tile
#define STAGE    (4 * TILEW)    // A_hi A_mid B_hi B_mid = 96KB
#define SMEM_REQ (2 * STAGE)    // 192KB double-buffered (1 CTA/SM)

__device__ __align__(128) float g_scratch[SPLITS * B_ * E_];
__device__ __align__(128) float g_emb[B_ * E_];

// ---------------------------------------------------------------------------
// Helpers
// ---------------------------------------------------------------------------
__device__ __forceinline__ uint32_t smem_u32(const void* p) {
    uint32_t a;
    asm("{ .reg .u64 t; cvta.to.shared.u64 t, %1; cvt.u32.u64 %0, t; }"
        : "=r"(a) : "l"(p));
    return a;
}

// 128x96 tile as 8x8 bf16 blocks (128B): block (br,bc) at (br*12+bc)*128,
// row j of block at 16B slot (j ^ (br&7) ^ ((bc&3)<<1)).
// LDSM phases (bc fixed, 8 rows) -> 8 distinct slots -> conflict-free.
// Fill STS phases (2 rows x 4 bc) -> 8 distinct slots -> conflict-free.
__device__ __forceinline__ uint32_t toff(int r, int c) {
    const int br = r >> 3, bc = c >> 3;
    const int slot = (r & 7) ^ (br & 7) ^ ((bc & 3) << 1);
    return (uint32_t)(((br * 12 + bc) << 7) + (slot << 4) + ((c & 7) << 1));
}

#define LDSM4(d, addr) \
    asm volatile("ldmatrix.sync.aligned.m8n8.x4.shared.b16 {%0,%1,%2,%3}, [%4];" \
        : "=r"((d)[0]), "=r"((d)[1]), "=r"((d)[2]), "=r"((d)[3]) : "r"(addr))

#define MMA16816(c, a, b0, b1) \
    asm volatile("mma.sync.aligned.m16n8k16.row.col.f32.bf16.bf16.f32 " \
        "{%0,%1,%2,%3}, {%4,%5,%6,%7}, {%8,%9}, {%0,%1,%2,%3};" \
        : "+f"((c)[0]), "+f"((c)[1]), "+f"((c)[2]), "+f"((c)[3]) \
        : "r"((a)[0]), "r"((a)[1]), "r"((a)[2]), "r"((a)[3]), "r"(b0), "r"(b1))

#define MMA16816_ZC(c, a, b0, b1, z) \
    asm volatile("mma.sync.aligned.m16n8k16.row.col.f32.bf16.bf16.f32 " \
        "{%0,%1,%2,%3}, {%4,%5,%6,%7}, {%8,%9}, {%10,%11,%12,%13};" \
        : "=f"((c)[0]), "=f"((c)[1]), "=f"((c)[2]), "=f"((c)[3]) \
        : "r"((a)[0]), "r"((a)[1]), "r"((a)[2]), "r"((a)[3]), "r"(b0), "r"(b1), \
          "f"(z), "f"(z), "f"(z), "f"(z))

#define STS128(addr, v) \
    asm volatile("st.shared.v4.b32 [%0], {%1, %2, %3, %4};" \
        :: "r"(addr), "r"((v).x), "r"((v).y), "r"((v).z), "r"((v).w) : "memory")

// 2-way bf16 split of 8 fp32 values -> two bf16x2-packed uint4.
__device__ __forceinline__ void split2(const float f[8], uint4& H, uint4& M) {
    uint32_t hw[4], mw[4];
#pragma unroll
    for (int i = 0; i < 4; i++) {
        const float f0 = f[2 * i], f1 = f[2 * i + 1];
        uint32_t hp;
        asm("cvt.rn.bf16x2.f32 %0, %1, %2;" : "=r"(hp) : "f"(f1), "f"(f0));
        const float h0 = __uint_as_float(hp << 16);
        const float h1 = __uint_as_float(hp & 0xFFFF0000u);
        const float r0 = f0 - h0, r1 = f1 - h1;   // exact (Sterbenz)
        uint32_t mp;
        asm("cvt.rn.bf16x2.f32 %0, %1, %2;" : "=r"(mp) : "f"(r1), "f"(r0));
        hw[i] = hp; mw[i] = mp;
    }
    H = make_uint4(hw[0], hw[1], hw[2], hw[3]);
    M = make_uint4(mw[0], mw[1], mw[2], mw[3]);
}

// ---------------------------------------------------------------------------
// Kernel 1: split-K GEMM via 3-pass bf16-split HMMA (xH@wH + xM@wH + xH@wM),
// per-chunk RN flush vs tensor-core RZ bias. 512 threads, 16 warps of 32x32,
// BKC=96 with three load/convert phases interleaved into the MMA body.
// (R15 configuration — calibrated best.)
// ---------------------------------------------------------------------------
__global__ __launch_bounds__(512) void gemm_hmma_kernel(
    const float* __restrict__ x, const float* __restrict__ W)
{
    extern __shared__ __align__(1024) char smem[];
    const uint32_t sm0 = smem_u32(smem);

    const int tid  = threadIdx.x;
    const int lane = tid & 31;
    const int wid  = tid >> 5;            // 0..15
    const int wm   = wid & 3;             // m tile: 32*wm
    const int wn   = wid >> 2;            // n tile: 32*wn

    const int brow  = blockIdx.x;         // 0..7
    const int bcol  = blockIdx.y;         // 0..1
    const int split = blockIdx.z;         // 0..SPLITS-1
    const int c0 = (split * NCHUNKS) / SPLITS;
    const int c1 = ((split + 1) * NCHUNKS) / SPLITS;

    const float* xrow = x + (size_t)(brow * MTILE) * V_;
    const float* wrow = W + (size_t)(bcol * NTILE) * V_;

    const int fr = tid >> 2;
    const int fq = tid & 3;

    const int jrA = ((lane >> 3) & 1) * 8 + (lane & 7);
    const int cA  = (lane >> 4) * 8;
    const int nB  = (lane >> 4) * 8 + (lane & 7);
    const int cB  = ((lane >> 3) & 1) * 8;

    float accm[2][4][4];                  // main accumulator (RN FADD)
    float acct[2][4][4];                  // HMMA chunk accumulator
#pragma unroll
    for (int i = 0; i < 2; i++)
#pragma unroll
        for (int j = 0; j < 4; j++)
#pragma unroll
            for (int q = 0; q < 4; q++) accm[i][j][q] = 0.f;

    const float fz = 0.f;
    float fA[8], fB[8];

    auto load_phase = [&](int c, int p) {
        const int kb = c * BKC + p * 32;
        const float* pa = xrow + (size_t)fr * V_ + kb + fq * 8;
        const float* pb = wrow + (size_t)fr * V_ + kb + fq * 8;
        if (kb + 32 <= V_) {
#pragma unroll
            for (int i = 0; i < 2; i++) {
                const float4 va = ((const float4*)pa)[i];
                const float4 vb = ((const float4*)pb)[i];
                fA[4 * i + 0] = va.x; fA[4 * i + 1] = va.y;
                fA[4 * i + 2] = va.z; fA[4 * i + 3] = va.w;
                fB[4 * i + 0] = vb.x; fB[4 * i + 1] = vb.y;
                fB[4 * i + 2] = vb.z; fB[4 * i + 3] = vb.w;
            }
        } else {
#pragma unroll
            for (int e = 0; e < 8; e++) {
                const bool ok = (kb + fq * 8 + e) < V_;
                fA[e] = ok ? pa[e] : 0.f;
                fB[e] = ok ? pb[e] : 0.f;
            }
        }
    };

    auto sts_phase = [&](uint32_t sb, int p) {
        const int bc = p * 4 + fq;
        const uint32_t o = (uint32_t)((((fr >> 3) * 12 + bc) << 7)
            + ((((fr & 7) ^ ((fr >> 3) & 7) ^ ((bc & 3) << 1))) << 4));
        uint4 H, M;
        split2(fA, H, M);
        STS128(sb + 0 * TILEW + o, H);
        STS128(sb + 1 * TILEW + o, M);
        split2(fB, H, M);
        STS128(sb + 2 * TILEW + o, H);
        STS128(sb + 3 * TILEW + o, M);
    };

    // prologue: fill stage 0 (all three phases)
#pragma unroll
    for (int p = 0; p < 3; p++) {
        load_phase(c0, p);
        sts_phase(sm0, p);
    }
    __syncthreads();

    for (int c = c0; c < c1; ++c) {
        const int li = c - c0;
        const uint32_t sb = sm0 + (uint32_t)(li & 1) * STAGE;
        const uint32_t sn = sm0 + (uint32_t)((li + 1) & 1) * STAGE;
        const bool more = (c + 1 < c1);

        if (more) load_phase(c + 1, 0);       // LDG phase 0 early

        // ---- 6 k-slices x 3 passes; converts interleaved at ki 0, 2, 4 ----
#pragma unroll
        for (int ki = 0; ki < 6; ki++) {
            const int k = ki * 16;
            uint32_t a[2][2][4];
#pragma unroll
            for (int lv = 0; lv < 2; lv++)
#pragma unroll
                for (int mt = 0; mt < 2; mt++)
                    LDSM4(a[lv][mt],
                          sb + lv * TILEW + toff(wm * 32 + mt * 16 + jrA, k + cA));

            uint32_t bH[2][4];
#pragma unroll
            for (int ng = 0; ng < 2; ng++)
                LDSM4(bH[ng], sb + 2 * TILEW
                              + toff(wn * 32 + ng * 16 + nB, k + cB));

            // group 1: A_hi x B_hi (ki==0 seeds the chunk accumulator)
            {
                const bool seed = (ki == 0);
#pragma unroll
                for (int mt = 0; mt < 2; mt++)
#pragma unroll
                    for (int nt = 0; nt < 4; nt++) {
                        if (seed)
                            MMA16816_ZC(acct[mt][nt], a[0][mt],
                                        bH[nt >> 1][(nt & 1) * 2],
                                        bH[nt >> 1][(nt & 1) * 2 + 1], fz);
                        else
                            MMA16816(acct[mt][nt], a[0][mt],
                                     bH[nt >> 1][(nt & 1) * 2],
                                     bH[nt >> 1][(nt & 1) * 2 + 1]);
                    }
            }
            // group 2: A_mid x B_hi
#pragma unroll
            for (int mt = 0; mt < 2; mt++)
#pragma unroll
                for (int nt = 0; nt < 4; nt++)
                    MMA16816(acct[mt][nt], a[1][mt],
                             bH[nt >> 1][(nt & 1) * 2],
                             bH[nt >> 1][(nt & 1) * 2 + 1]);

            uint32_t bM[2][4];
#pragma unroll
            for (int ng = 0; ng < 2; ng++)
                LDSM4(bM[ng], sb + 3 * TILEW
                              + toff(wn * 32 + ng * 16 + nB, k + cB));

            // group 3: A_hi x B_mid
#pragma unroll
            for (int mt = 0; mt < 2; mt++)
#pragma unroll
                for (int nt = 0; nt < 4; nt++)
                    MMA16816(acct[mt][nt], a[0][mt],
                             bM[nt >> 1][(nt & 1) * 2],
                             bM[nt >> 1][(nt & 1) * 2 + 1]);

            // interleave next-chunk converts while MMAs drain
            if (more && ki == 0) {
                sts_phase(sn, 0);
                load_phase(c + 1, 1);
            }
            if (more && ki == 2) {
                sts_phase(sn, 1);
                load_phase(c + 1, 2);
            }
            if (more && ki == 4) {
                sts_phase(sn, 2);
            }
        }

        // chunk flush: RN fp32 adds (defeats tensor-core RZ bias)
#pragma unroll
        for (int mt = 0; mt < 2; mt++)
#pragma unroll
            for (int nt = 0; nt < 4; nt++)
#pragma unroll
                for (int q = 0; q < 4; q++)
                    accm[mt][nt][q] += acct[mt][nt][q];

        __syncthreads();
    }

    // epilogue: write fp32 partials
    float* base = g_scratch + (size_t)split * (B_ * E_);
#pragma unroll
    for (int mt = 0; mt < 2; mt++)
#pragma unroll
        for (int nt = 0; nt < 4; nt++) {
            const int row = brow * MTILE + wm * 32 + mt * 16 + (lane >> 2);
            const int col = bcol * NTILE + wn * 32 + nt * 8 + (lane & 3) * 2;
            float2 v0 = make_float2(accm[mt][nt][0], accm[mt][nt][1]);
            float2 v1 = make_float2(accm[mt][nt][2], accm[mt][nt][3]);
            *(float2*)&base[(size_t)row * E_ + col]       = v0;
            *(float2*)&base[(size_t)(row + 8) * E_ + col] = v1;
        }
}

// ---------------------------------------------------------------------------
// Kernel 2: deterministic split-K reduction + bias -> g_emb
// ---------------------------------------------------------------------------
__global__ __launch_bounds__(256) void reduce_bias_kernel(const float* __restrict__ bias)
{
    const int idx = blockIdx.x * blockDim.x + threadIdx.x;   // < B_*E_/4
    const float4* sc = (const float4*)g_scratch;
    float4 s = make_float4(0.f, 0.f, 0.f, 0.f);
#pragma unroll
    for (int sp = 0; sp < SPLITS; sp++) {
        const float4 v = sc[(size_t)sp * (B_ * E_ / 4) + idx];
        s.x += v.x; s.y += v.y; s.z += v.z; s.w += v.w;
    }
    const float4 bb = ((const float4*)bias)[idx & (E_ / 4 - 1)];
    s.x += bb.x; s.y += bb.y; s.z += bb.z; s.w += bb.w;
    ((float4*)g_emb)[idx] = s;
}

// ---------------------------------------------------------------------------
// Kernel 3: per-path dots, signed sigmoid, product; deterministic combine.
// Pairs of path nodes processed together (2x memory-level parallelism);
// multiply order kept identical to the sequential version.
// ---------------------------------------------------------------------------
__global__ __launch_bounds__(128) void path_prod_kernel(
    const float* __restrict__ pv, const int* __restrict__ signs,
    float* __restrict__ out)
{
    __shared__ float part[4];
    const int warp = threadIdx.x >> 5;
    const int lane = threadIdx.x & 31;
    const int b    = blockIdx.x;

    float e[8];
#pragma unroll
    for (int j = 0; j < 8; j++)
        e[j] = g_emb[b * E_ + lane + 32 * j];

    const int l0 = (warp == 0) ? 0 : (5 + (warp - 1) * 4);
    const int l1 = (warp == 0) ? 5 : (l0 + 4);

    auto sigmoid_stable = [](float logit) -> float {
        if (logit >= 0.f) return 1.f / (1.f + expf(-logit));
        const float ex = expf(logit);
        return ex / (1.f + ex);
    };

    float prod = 1.f;
    int l = l0;
#pragma unroll 1
    for (; l + 1 < l1; l += 2) {
        const float* p0 = pv + ((size_t)b * L_ + l) * E_;
        const float* p1 = p0 + E_;
        const int sg0 = signs[b * L_ + l];
        const int sg1 = signs[b * L_ + l + 1];

        // both vector streams in flight before either reduction
        float q0[8], q1[8];
#pragma unroll
        for (int j = 0; j < 8; j++) q0[j] = p0[lane + 32 * j];
#pragma unroll
        for (int j = 0; j < 8; j++) q1[j] = p1[lane + 32 * j];

        float d0 = 0.f, d1 = 0.f;
#pragma unroll
        for (int j = 0; j < 8; j++) { d0 += q0[j] * e[j]; d1 += q1[j] * e[j]; }
#pragma unroll
        for (int off = 16; off; off >>= 1) {
            d0 += __shfl_xor_sync(0xFFFFFFFFu, d0, off);
            d1 += __shfl_xor_sync(0xFFFFFFFFu, d1, off);
        }

        prod *= sigmoid_stable(d0 * (float)(2 * sg0 - 1));
        prod *= sigmoid_stable(d1 * (float)(2 * sg1 - 1));
    }
    if (l < l1) {   // odd remainder (warp 0's 5th node)
        const float* p = pv + ((size_t)b * L_ + l) * E_;
        float d = 0.f;
#pragma unroll
        for (int j = 0; j < 8; j++)
            d += p[lane + 32 * j] * e[j];
#pragma unroll
        for (int off = 16; off; off >>= 1)
            d += __shfl_xor_sync(0xFFFFFFFFu, d, off);
        const int sg = signs[b * L_ + l];
        prod *= sigmoid_stable(d * (float)(2 * sg - 1));
    }

    if (lane == 0) part[warp] = prod;
    __syncthreads();
    if (threadIdx.x == 0)
        out[b] = ((part[0] * part[1]) * part[2]) * part[3];
}

// ---------------------------------------------------------------------------
// Launch. Inputs (metadata order): x[B*V], W[E*V], b[E], path_vectors[B*L*E],
// path_signs[B*L] (int32). Output: float[B].
// ---------------------------------------------------------------------------
extern "C" void kernel_launch(void* const* d_in, const int* in_sizes, int n_in,
                              void* d_out, int out_size)
{
    const float* x     = (const float*)d_in[0];
    const float* W     = (const float*)d_in[1];
    const float* bias  = (const float*)d_in[2];
    const float* pv    = (const float*)d_in[3];
    const int*   signs = (const int*)  d_in[4];
    float*       out   = (float*)d_out;

    // idempotent attribute set (not a stream op; capture-safe)
    cudaFuncSetAttribute(gemm_hmma_kernel,
                         cudaFuncAttributeMaxDynamicSharedMemorySize, SMEM_REQ);

    dim3 g1(B_ / MTILE, E_ / NTILE, SPLITS);   // (8, 2, 9) = 144 CTAs
    gemm_hmma_kernel<<<g1, 512, SMEM_REQ>>>(x, W);

    reduce_bias_kernel<<<(B_ * E_ / 4) / 256, 256>>>(bias);

    path_prod_kernel<<<B_, 128>>>(pv, signs, out);
}